// round 5
// baseline (speedup 1.0000x reference)
#include <cuda_runtime.h>
#include <cstdint>

// Shape: inp:[2048,2048,3] f32, w_ih:[96,3], w_hh:[96,32], bias:[96], bias_n:[32]
// out:[2048,2048,1] f32 (h[0] each step)
#define TT 2048
#define BB 2048
#define WARPS_PER_BLK 4   // one warp per SMSP, by construction (wid % 4)

__device__ __forceinline__ void ffma2(unsigned long long &d,
                                      unsigned long long a,
                                      unsigned long long b) {
    asm("fma.rn.f32x2 %0, %1, %2, %0;" : "+l"(d) : "l"(a), "l"(b));
}

__device__ __forceinline__ float2 unpack2(unsigned long long v) {
    float2 r;
    asm("mov.b64 {%0, %1}, %2;" : "=f"(r.x), "=f"(r.y) : "l"(v));
    return r;
}

__device__ __forceinline__ float sigmoid_fast(float x) {
    return __fdividef(1.0f, 1.0f + __expf(-x));
}
__device__ __forceinline__ float tanh_fast2(float x) {
    return __fdividef(2.0f, 1.0f + __expf(-2.0f * x)) - 1.0f;
}

// 4 warps/block, one sequence per warp, lane j owns hidden unit j.
// W_hh rows live in registers (48 packed f32x2/lane). h is broadcast through a
// per-warp double-buffered smem vector read back as u64 pairs (LDS.64 feeds
// fma.rn.f32x2 directly). One __syncwarp per step; warps never interact.
__global__ void __launch_bounds__(128, 4)
gru_warp_kernel(const float* __restrict__ inp,
                const float* __restrict__ w_ih,
                const float* __restrict__ w_hh,
                const float* __restrict__ bias,
                const float* __restrict__ bias_n,
                float* __restrict__ out) {
    __shared__ __align__(8) float hbuf[WARPS_PER_BLK][2][32];
    __shared__ float xbuf[WARPS_PER_BLK][96];  // 32 timesteps of x per warp

    const int j  = threadIdx.x & 31;                     // hidden unit
    const int w  = threadIdx.x >> 5;                     // warp in block -> SMSP
    const int b  = blockIdx.x * WARPS_PER_BLK + w;       // sequence index

    // ---- per-lane weights into registers (one-time) ----
    unsigned long long wr[16], wz[16], wa[16];
    {
        const unsigned long long* rr =
            reinterpret_cast<const unsigned long long*>(w_hh + (0 * 32 + j) * 32);
        const unsigned long long* rz =
            reinterpret_cast<const unsigned long long*>(w_hh + (1 * 32 + j) * 32);
        const unsigned long long* ra =
            reinterpret_cast<const unsigned long long*>(w_hh + (2 * 32 + j) * 32);
#pragma unroll
        for (int k = 0; k < 16; k++) { wr[k] = rr[k]; wz[k] = rz[k]; wa[k] = ra[k]; }
    }
    const float wir0 = w_ih[(0 * 32 + j) * 3 + 0];
    const float wir1 = w_ih[(0 * 32 + j) * 3 + 1];
    const float wir2 = w_ih[(0 * 32 + j) * 3 + 2];
    const float wiz0 = w_ih[(1 * 32 + j) * 3 + 0];
    const float wiz1 = w_ih[(1 * 32 + j) * 3 + 1];
    const float wiz2 = w_ih[(1 * 32 + j) * 3 + 2];
    const float wia0 = w_ih[(2 * 32 + j) * 3 + 0];
    const float wia1 = w_ih[(2 * 32 + j) * 3 + 1];
    const float wia2 = w_ih[(2 * 32 + j) * 3 + 2];
    const float br  = bias[0 * 32 + j];
    const float bz  = bias[1 * 32 + j];
    const float ban = bias[2 * 32 + j] + bias_n[j];  // fold bias_n into a-gate bias

    float h = 0.0f;
    const float* gx   = inp + (size_t)b * (TT * 3);
    float*       gout = out + (size_t)b * TT;

    float* myh0 = hbuf[w][0];
    float* myh1 = hbuf[w][1];
    float* myx  = xbuf[w];

    for (int t = 0; t < TT; t++) {
        // Refill 32 timesteps of input cooperatively (coalesced, 3 LDG/lane).
        if ((t & 31) == 0) {
            __syncwarp();  // previous chunk's readers are done
            const int base = t * 3;
            myx[j]      = gx[base + j];
            myx[32 + j] = gx[base + 32 + j];
            myx[64 + j] = gx[base + 64 + j];
        }

        // Publish h_t, then read the whole vector back (broadcast LDS.64).
        float* cur = (t & 1) ? myh1 : myh0;
        cur[j] = h;
        __syncwarp();

        const int ti = (t & 31) * 3;
        const float x0 = myx[ti + 0];
        const float x1 = myx[ti + 1];
        const float x2 = myx[ti + 2];
        const float ir = fmaf(wir2, x2, fmaf(wir1, x1, fmaf(wir0, x0, br)));
        const float iz = fmaf(wiz2, x2, fmaf(wiz1, x1, fmaf(wiz0, x0, bz)));
        const float ia = fmaf(wia2, x2, fmaf(wia1, x1, fmaf(wia0, x0, ban)));

        // Seed r/z accumulators with the input gate (saves the final FADD).
        unsigned long long accr = (unsigned long long)__float_as_uint(ir);
        unsigned long long accz = (unsigned long long)__float_as_uint(iz);
        unsigned long long acca = 0ull;  // a-gate hidden part stays pure (scaled by r)

        const unsigned long long* hp64 =
            reinterpret_cast<const unsigned long long*>(cur);
#pragma unroll
        for (int k = 0; k < 16; k++) {
            const unsigned long long hp = hp64[k];
            ffma2(accr, wr[k], hp);
            ffma2(accz, wz[k], hp);
            ffma2(acca, wa[k], hp);
        }
        const float2 fr = unpack2(accr);
        const float2 fz = unpack2(accz);
        const float2 fa = unpack2(acca);

        const float r = sigmoid_fast(fr.x + fr.y);
        const float z = sigmoid_fast(fz.x + fz.y);
        const float n = tanh_fast2(fmaf(r, fa.x + fa.y, ia));
        h = fmaf(z, h - n, n);   // (1-z)*n + z*h

        if (j == 0) gout[t] = h;
    }
}

extern "C" void kernel_launch(void* const* d_in, const int* in_sizes, int n_in,
                              void* d_out, int out_size) {
    const float* inp    = (const float*)d_in[0];
    const float* w_ih   = (const float*)d_in[1];
    const float* w_hh   = (const float*)d_in[2];
    const float* bias   = (const float*)d_in[3];
    const float* bias_n = (const float*)d_in[4];
    float* out = (float*)d_out;
    gru_warp_kernel<<<BB / WARPS_PER_BLK, 32 * WARPS_PER_BLK>>>(
        inp, w_ih, w_hh, bias, bias_n, out);
}

// round 6
// speedup vs baseline: 1.1957x; 1.1957x over previous
#include <cuda_runtime.h>
#include <cstdint>

// Shape: inp:[2048,2048,3] f32, w_ih:[96,3], w_hh:[96,32], bias:[96], bias_n:[32]
// out:[2048,2048,1] f32 (h[0] each step)
#define TT 2048
#define BB 2048

__device__ __forceinline__ void ffma2(unsigned long long &d,
                                      unsigned long long a,
                                      unsigned long long b) {
    asm("fma.rn.f32x2 %0, %1, %2, %0;" : "+l"(d) : "l"(a), "l"(b));
}

__device__ __forceinline__ float2 unpack2(unsigned long long v) {
    float2 r;
    asm("mov.b64 {%0, %1}, %2;" : "=f"(r.x), "=f"(r.y) : "l"(v));
    return r;
}

// Single-MUFU tanh (lat 16) — used for r-gate and candidate n.
__device__ __forceinline__ float tanh_hw(float x) {
    float y;
    asm("tanh.approx.f32 %0, %1;" : "=f"(y) : "f"(x));
    return y;
}
// Approx sigmoid via MUFU.TANH: sigma(x) = 0.5 + 0.5*tanh(x/2).
__device__ __forceinline__ float sigmoid_hw(float x) {
    return fmaf(0.5f, tanh_hw(0.5f * x), 0.5f);
}
// Accurate sigmoid (EX2+RCP, ~1e-7) — kept for the carry gate z.
__device__ __forceinline__ float sigmoid_acc(float x) {
    return __fdividef(1.0f, 1.0f + __expf(-x));
}

// One warp per sequence; lane j owns hidden unit j. W_hh in registers as 48
// packed f32x2/lane. h broadcast via double-buffered smem, read back with
// 8x ld.shared.v2.u64 (128-bit). One WARPSYNC per step. Input x staged in
// smem in 32-step chunks with register prefetch of the next chunk.
__global__ void __launch_bounds__(32, 14)
gru_warp_kernel(const float* __restrict__ inp,
                const float* __restrict__ w_ih,
                const float* __restrict__ w_hh,
                const float* __restrict__ bias,
                const float* __restrict__ bias_n,
                float* __restrict__ out) {
    __shared__ __align__(16) float hbuf[2][32];
    __shared__ float xbuf[96];  // 32 timesteps of x (3 floats each)

    const int j = threadIdx.x;   // hidden unit index 0..31
    const int b = blockIdx.x;    // sequence index

    // ---- per-lane weights into registers (one-time) ----
    unsigned long long wr[16], wz[16], wa[16];
    {
        const unsigned long long* rr =
            reinterpret_cast<const unsigned long long*>(w_hh + (0 * 32 + j) * 32);
        const unsigned long long* rz =
            reinterpret_cast<const unsigned long long*>(w_hh + (1 * 32 + j) * 32);
        const unsigned long long* ra =
            reinterpret_cast<const unsigned long long*>(w_hh + (2 * 32 + j) * 32);
#pragma unroll
        for (int k = 0; k < 16; k++) { wr[k] = rr[k]; wz[k] = rz[k]; wa[k] = ra[k]; }
    }
    const float wir0 = w_ih[(0 * 32 + j) * 3 + 0];
    const float wir1 = w_ih[(0 * 32 + j) * 3 + 1];
    const float wir2 = w_ih[(0 * 32 + j) * 3 + 2];
    const float wiz0 = w_ih[(1 * 32 + j) * 3 + 0];
    const float wiz1 = w_ih[(1 * 32 + j) * 3 + 1];
    const float wiz2 = w_ih[(1 * 32 + j) * 3 + 2];
    const float wia0 = w_ih[(2 * 32 + j) * 3 + 0];
    const float wia1 = w_ih[(2 * 32 + j) * 3 + 1];
    const float wia2 = w_ih[(2 * 32 + j) * 3 + 2];
    const float br  = bias[0 * 32 + j];
    const float bz  = bias[1 * 32 + j];
    const float ban = bias[2 * 32 + j] + bias_n[j];  // fold bias_n into a-gate

    float h = 0.0f;
    const float* gx   = inp + (size_t)b * (TT * 3);
    float*       gout = out + (size_t)b * TT;

    // Prefetch chunk 0 into registers.
    float p0 = gx[j], p1 = gx[32 + j], p2 = gx[64 + j];

    for (int t = 0; t < TT; t++) {
        if ((t & 31) == 0) {
            __syncwarp();          // previous chunk's xbuf readers done
            xbuf[j]      = p0;
            xbuf[32 + j] = p1;
            xbuf[64 + j] = p2;
            const int nb = (t + 32) * 3;
            if (nb < TT * 3) {     // prefetch next chunk (LDG hidden over 32 steps)
                p0 = gx[nb + j];
                p1 = gx[nb + 32 + j];
                p2 = gx[nb + 64 + j];
            }
        }

        // Publish h_t, then read whole vector back (broadcast LDS.128).
        float* cur = hbuf[t & 1];
        cur[j] = h;
        __syncwarp();

        const int ti = (t & 31) * 3;
        const float x0 = xbuf[ti + 0];
        const float x1 = xbuf[ti + 1];
        const float x2 = xbuf[ti + 2];
        const float ir = fmaf(wir2, x2, fmaf(wir1, x1, fmaf(wir0, x0, br)));
        const float iz = fmaf(wiz2, x2, fmaf(wiz1, x1, fmaf(wiz0, x0, bz)));
        const float ia = fmaf(wia2, x2, fmaf(wia1, x1, fmaf(wia0, x0, ban)));

        // Hidden matvec: 3 gates x 32 MACs as 48 dual FMAs, h pairs via
        // 128-bit shared loads (two u64 per load -> feeds f32x2 directly).
        unsigned long long accr = 0ull, accz = 0ull, acca = 0ull;
        const ulonglong2* hp128 = reinterpret_cast<const ulonglong2*>(cur);
#pragma unroll
        for (int q = 0; q < 8; q++) {
            const ulonglong2 hp = hp128[q];
            ffma2(accr, wr[2 * q],     hp.x);
            ffma2(accz, wz[2 * q],     hp.x);
            ffma2(acca, wa[2 * q],     hp.x);
            ffma2(accr, wr[2 * q + 1], hp.y);
            ffma2(accz, wz[2 * q + 1], hp.y);
            ffma2(acca, wa[2 * q + 1], hp.y);
        }
        const float2 fr = unpack2(accr);
        const float2 fz = unpack2(accz);
        const float2 fa = unpack2(acca);

        const float r = sigmoid_hw(ir + (fr.x + fr.y));   // MUFU.TANH path
        const float z = sigmoid_acc(iz + (fz.x + fz.y));  // accurate carry gate
        const float n = tanh_hw(fmaf(r, fa.x + fa.y, ia)); // MUFU.TANH
        h = fmaf(z, h - n, n);   // (1-z)*n + z*h

        if (j == 0) gout[t] = h;
    }
}

extern "C" void kernel_launch(void* const* d_in, const int* in_sizes, int n_in,
                              void* d_out, int out_size) {
    const float* inp    = (const float*)d_in[0];
    const float* w_ih   = (const float*)d_in[1];
    const float* w_hh   = (const float*)d_in[2];
    const float* bias   = (const float*)d_in[3];
    const float* bias_n = (const float*)d_in[4];
    float* out = (float*)d_out;
    gru_warp_kernel<<<BB, 32>>>(inp, w_ih, w_hh, bias, bias_n, out);
}